// round 12
// baseline (speedup 1.0000x reference)
#include <cuda_runtime.h>
#include <cuda_bf16.h>
#include <cuda_fp16.h>
#include <cstdint>

#define BATCH 256
#define INF   1024
#define OUTF  128
#define KD    8
#define NCOLS (OUTF * KD)     // 1024
#define OUTW  (INF + OUTF)    // 1152

// Device scratch (no allocs allowed)
__device__ __align__(16) __half g_Mh[BATCH * NCOLS];   // M = x @ T, fp16
__device__ __nv_bfloat16 g_Abf[BATCH * INF];           // x in bf16 (K-major)
__device__ __nv_bfloat16 g_Tbf[INF * NCOLS];           // T in bf16, [k][n] layout

__device__ __forceinline__ uint32_t smem_u32(const void* p) {
    uint32_t a;
    asm("{ .reg .u64 t; cvta.to.shared.u64 t, %1; cvt.u32.u64 %0, t; }" : "=r"(a) : "l"(p));
    return a;
}
#define SWZ128(b) ((b) ^ (((b) >> 3) & 0x70))
#define CP_ASYNC16(saddr, gptr) \
    asm volatile("cp.async.cg.shared.global [%0], [%1], 16;" :: "r"(saddr), "l"(gptr) : "memory")
#define CP_COMMIT() asm volatile("cp.async.commit_group;" ::: "memory")
#define CP_WAIT1()  asm volatile("cp.async.wait_group 1;" ::: "memory")

// ---------------------------------------------------------------------------
// Streaming prep (R8-identical):
//   blocks [0,1024):    T fp32 -> bf16, layout unchanged [k][n]
//   blocks [1024,1280): copy x into out[:, :1024] + convert x -> bf16
// ---------------------------------------------------------------------------
__global__ __launch_bounds__(256) void prep_kernel(
    const float* __restrict__ x, const float* __restrict__ T,
    float* __restrict__ out, __nv_bfloat16* __restrict__ xb,
    __nv_bfloat16* __restrict__ Tb)
{
    if (blockIdx.x < 1024) {
        const int idx = blockIdx.x * 256 + threadIdx.x;   // float4 index in T
        const float4 v = reinterpret_cast<const float4*>(T)[idx];
        reinterpret_cast<__nv_bfloat162*>(Tb)[idx * 2]     = __floats2bfloat162_rn(v.x, v.y);
        reinterpret_cast<__nv_bfloat162*>(Tb)[idx * 2 + 1] = __floats2bfloat162_rn(v.z, v.w);
    } else {
        const int idx = (blockIdx.x - 1024) * 256 + threadIdx.x;  // float4 index in x
        const float4 v = reinterpret_cast<const float4*>(x)[idx];
        const int row = idx >> 8;
        const int c4  = idx & 255;
        *reinterpret_cast<float4*>(&out[row * OUTW + c4 * 4]) = v;
        reinterpret_cast<__nv_bfloat162*>(xb)[idx * 2]     = __floats2bfloat162_rn(v.x, v.y);
        reinterpret_cast<__nv_bfloat162*>(xb)[idx * 2 + 1] = __floats2bfloat162_rn(v.z, v.w);
    }
}

// ---------------------------------------------------------------------------
// HMMA GEMM (R8-identical), 3-stage cp.async; B via ldmatrix.trans on [k][n].
// CTA tile M=32 x N=64, BK=64 (16 chunks). Grid (16 nt, 8 mt) = 128 CTAs.
// ---------------------------------------------------------------------------
#define STAGE_BYTES 12288
#define GEMM_SMEM   (3 * STAGE_BYTES)

__global__ __launch_bounds__(256) void gemm_mma_kernel(
    const __nv_bfloat16* __restrict__ A, const __nv_bfloat16* __restrict__ Tb,
    __half* __restrict__ C)
{
    extern __shared__ __align__(1024) char dsm[];

    const int tid = threadIdx.x;
    const int wid = tid >> 5;
    const int lid = tid & 31;
    const int nt = blockIdx.x;
    const int mt = blockIdx.y;
    const int w_m = wid >> 2;
    const int w_n = wid & 3;

    const uint32_t sbase = smem_u32(dsm);

    const __nv_bfloat16* Ag = A + (size_t)(mt * 32) * INF;
    const __nv_bfloat16* Bg = Tb + nt * 64;

    const int ld_row  = tid >> 3;
    const int ld_kc   = tid & 7;
    const uint32_t soff0 = SWZ128((uint32_t)(ld_row * 128 + ld_kc * 16));
    const uint32_t soff1 = SWZ128((uint32_t)((ld_row + 32) * 128 + ld_kc * 16));

    float c[2][4];
    #pragma unroll
    for (int j = 0; j < 2; j++)
        #pragma unroll
        for (int q = 0; q < 4; q++) c[j][q] = 0.0f;

    const int l7  = lid & 7;
    const int lb3 = (lid >> 3) & 1;
    const int lb4 = (lid >> 4) & 1;
    const int a_row_lane = l7 + lb3 * 8;
    const int b_row_lane = l7 + lb3 * 8;
    const int nb = w_n * 16;
    const int mb = w_m * 16;
    const uint32_t b_col_bytes = (uint32_t)(nb + 8 * lb4) * 2;

    auto load_stage = [&](int st, int k0) {
        const uint32_t sA = sbase + st * STAGE_BYTES;
        const uint32_t sB = sA + 4096;
        const __nv_bfloat16* ga = Ag + ld_row * INF + k0 + ld_kc * 8;
        const __nv_bfloat16* gb = Bg + (size_t)(k0 + ld_row) * NCOLS + ld_kc * 8;
        CP_ASYNC16(sA + soff0, ga);
        CP_ASYNC16(sB + soff0, gb);
        CP_ASYNC16(sB + soff1, gb + 32 * NCOLS);
    };

    load_stage(0, 0);   CP_COMMIT();
    load_stage(1, 64);  CP_COMMIT();

    for (int ch = 0; ch < 16; ch++) {
        CP_WAIT1();
        __syncthreads();
        if (ch + 2 < 16) load_stage((ch + 2) % 3, (ch + 2) * 64);
        CP_COMMIT();

        const uint32_t sA = sbase + (ch % 3) * STAGE_BYTES;
        const uint32_t sB = sA + 4096;

        #pragma unroll
        for (int s = 0; s < 4; s++) {
            uint32_t b0, b1, b2, b3;
            {
                const uint32_t boff = SWZ128(
                    (uint32_t)((s * 16 + b_row_lane) * 128) + b_col_bytes);
                asm volatile(
                    "ldmatrix.sync.aligned.m8n8.x4.trans.shared.b16 {%0,%1,%2,%3}, [%4];"
                    : "=r"(b0), "=r"(b1), "=r"(b2), "=r"(b3) : "r"(sB + boff));
            }
            uint32_t a0, a1, a2, a3;
            {
                const uint32_t aoff = SWZ128(
                    (uint32_t)((mb + a_row_lane) * 128 + (s * 2 + lb4) * 16));
                asm volatile(
                    "ldmatrix.sync.aligned.m8n8.x4.shared.b16 {%0,%1,%2,%3}, [%4];"
                    : "=r"(a0), "=r"(a1), "=r"(a2), "=r"(a3) : "r"(sA + aoff));
            }
            asm volatile(
                "mma.sync.aligned.m16n8k16.row.col.f32.bf16.bf16.f32 "
                "{%0,%1,%2,%3}, {%4,%5,%6,%7}, {%8,%9}, {%0,%1,%2,%3};"
                : "+f"(c[0][0]), "+f"(c[0][1]), "+f"(c[0][2]), "+f"(c[0][3])
                : "r"(a0), "r"(a1), "r"(a2), "r"(a3), "r"(b0), "r"(b1));
            asm volatile(
                "mma.sync.aligned.m16n8k16.row.col.f32.bf16.bf16.f32 "
                "{%0,%1,%2,%3}, {%4,%5,%6,%7}, {%8,%9}, {%0,%1,%2,%3};"
                : "+f"(c[1][0]), "+f"(c[1][1]), "+f"(c[1][2]), "+f"(c[1][3])
                : "r"(a0), "r"(a1), "r"(a2), "r"(a3), "r"(b2), "r"(b3));
        }
    }

    const int g = lid >> 2;
    const int tig = lid & 3;
    const int row = mt * 32 + mb + g;
    #pragma unroll
    for (int nf = 0; nf < 2; nf++) {
        const int col = nt * 64 + nb + nf * 8 + tig * 2;
        *reinterpret_cast<__half2*>(&C[row * NCOLS + col]) =
            __floats2half2_rn(c[nf][0], c[nf][1]);
        *reinterpret_cast<__half2*>(&C[(row + 8) * NCOLS + col]) =
            __floats2half2_rn(c[nf][2], c[nf][3]);
    }
}

// ---------------------------------------------------------------------------
// Pairwise L1 + exp-sum, fp16x2 with single-MUFU ex2.approx.f16x2.
// Grid 512 = (o, i-quarter). 512 threads = 64 i-local x 8-way j-split (32 j).
// ---------------------------------------------------------------------------
__global__ __launch_bounds__(512) void pairwise_kernel(
    const __half* __restrict__ Mh, float* __restrict__ out)
{
    const int o  = blockIdx.x >> 2;
    const int iq = blockIdx.x & 3;
    const int il = threadIdx.x & 63;
    const int h  = threadIdx.x >> 6;
    const int i  = iq * 64 + il;

    __shared__ uint4 Ms[BATCH];
    __shared__ float psum[7][64];

    if (threadIdx.x < BATCH)
        Ms[threadIdx.x] = *reinterpret_cast<const uint4*>(
            &Mh[threadIdx.x * NCOLS + o * KD]);
    __syncthreads();

    uint4 av = Ms[i];
    const __half2 a0 = *reinterpret_cast<__half2*>(&av.x);
    const __half2 a1 = *reinterpret_cast<__half2*>(&av.y);
    const __half2 a2 = *reinterpret_cast<__half2*>(&av.z);
    const __half2 a3 = *reinterpret_cast<__half2*>(&av.w);

    const __half2 nlog2e = __float2half2_rn(-1.44269504089f);
    __half2 acc = __float2half2_rn(0.0f);

    const int j0 = h * 32;
    #pragma unroll 8
    for (int j = j0; j < j0 + 32; j++) {
        uint4 bv = Ms[j];   // warp-uniform j -> LDS broadcast
        const __half2 s0 = __hsub2(a0, *reinterpret_cast<__half2*>(&bv.x));
        const __half2 s1 = __hsub2(a1, *reinterpret_cast<__half2*>(&bv.y));
        const __half2 s2 = __hsub2(a2, *reinterpret_cast<__half2*>(&bv.z));
        const __half2 s3 = __hsub2(a3, *reinterpret_cast<__half2*>(&bv.w));
        const __half2 t = __hadd2(__hadd2(__habs2(s0), __habs2(s1)),
                                  __hadd2(__habs2(s2), __habs2(s3)));
        const __half2 d = __hadd2(t, __lowhigh2highlow(t));   // full dist, both lanes
        const __half2 arg = __hmul2(d, nlog2e);               // -d * log2(e)
        __half2 e;
        asm("ex2.approx.f16x2 %0, %1;"
            : "=r"(*reinterpret_cast<uint32_t*>(&e))
            : "r"(*reinterpret_cast<const uint32_t*>(&arg)));  // exp(-d), 1 MUFU
        acc = __hadd2(acc, e);
    }

    const float s = __low2float(acc);

    if (h) psum[h - 1][il] = s;
    __syncthreads();
    if (h == 0) {
        float tot = s - 1.0f;
        #pragma unroll
        for (int q = 0; q < 7; q++) tot += psum[q][il];
        out[i * OUTW + INF + o] = tot;
    }
}

// ---------------------------------------------------------------------------
extern "C" void kernel_launch(void* const* d_in, const int* in_sizes, int n_in,
                              void* d_out, int out_size)
{
    const float* x = (const float*)d_in[0];   // (256, 1024)
    const float* T = (const float*)d_in[1];   // (1024, 1024)
    float* out = (float*)d_out;               // (256, 1152)

    __half* Mh;
    __nv_bfloat16 *Abf, *Tbf;
    cudaGetSymbolAddress((void**)&Mh, g_Mh);
    cudaGetSymbolAddress((void**)&Abf, g_Abf);
    cudaGetSymbolAddress((void**)&Tbf, g_Tbf);

    static bool attr_set = false;
    if (!attr_set) {
        cudaFuncSetAttribute(gemm_mma_kernel,
                             cudaFuncAttributeMaxDynamicSharedMemorySize, GEMM_SMEM);
        attr_set = true;
    }

    prep_kernel<<<1024 + 256, 256>>>(x, T, out, Abf, Tbf);

    gemm_mma_kernel<<<dim3(NCOLS / 64, BATCH / 32), 256, GEMM_SMEM>>>(Abf, Tbf, Mh);

    pairwise_kernel<<<4 * OUTF, 512>>>(Mh, out);
}

// round 13
// speedup vs baseline: 1.4150x; 1.4150x over previous
#include <cuda_runtime.h>
#include <cuda_bf16.h>
#include <cuda_fp16.h>
#include <cstdint>

#define BATCH 256
#define INF   1024
#define OUTF  128
#define KD    8
#define NCOLS (OUTF * KD)     // 1024
#define OUTW  (INF + OUTF)    // 1152

// Device scratch (no allocs allowed)
__device__ __align__(16) __half g_Mh[BATCH * NCOLS];   // Mh = (x @ T) * log2(e), fp16
__device__ __nv_bfloat16 g_Abf[BATCH * INF];           // x in bf16 (K-major)
__device__ __nv_bfloat16 g_Tbf[INF * NCOLS];           // T in bf16, [k][n] layout

__device__ __forceinline__ uint32_t smem_u32(const void* p) {
    uint32_t a;
    asm("{ .reg .u64 t; cvta.to.shared.u64 t, %1; cvt.u32.u64 %0, t; }" : "=r"(a) : "l"(p));
    return a;
}
#define SWZ128(b) ((b) ^ (((b) >> 3) & 0x70))
#define CP_ASYNC16(saddr, gptr) \
    asm volatile("cp.async.cg.shared.global [%0], [%1], 16;" :: "r"(saddr), "l"(gptr) : "memory")
#define CP_COMMIT() asm volatile("cp.async.commit_group;" ::: "memory")
#define CP_WAIT1()  asm volatile("cp.async.wait_group 1;" ::: "memory")

// ---------------------------------------------------------------------------
// Streaming prep, MLP=4, 320 blocks:
//   blocks [0,256):   T fp32 -> bf16 (layout unchanged), 4 float4/thread
//   blocks [256,320): x -> out[:, :1024] copy + x -> bf16, 4 float4/thread
// ---------------------------------------------------------------------------
__global__ __launch_bounds__(256) void prep_kernel(
    const float* __restrict__ x, const float* __restrict__ T,
    float* __restrict__ out, __nv_bfloat16* __restrict__ xb,
    __nv_bfloat16* __restrict__ Tb)
{
    const int tid = threadIdx.x;
    float4 v[4];
    if (blockIdx.x < 256) {
        const int base = blockIdx.x * 1024 + tid;
        #pragma unroll
        for (int r = 0; r < 4; r++)
            v[r] = reinterpret_cast<const float4*>(T)[base + r * 256];
        #pragma unroll
        for (int r = 0; r < 4; r++) {
            const int idx = base + r * 256;
            reinterpret_cast<__nv_bfloat162*>(Tb)[idx * 2] =
                __floats2bfloat162_rn(v[r].x, v[r].y);
            reinterpret_cast<__nv_bfloat162*>(Tb)[idx * 2 + 1] =
                __floats2bfloat162_rn(v[r].z, v[r].w);
        }
    } else {
        const int base = (blockIdx.x - 256) * 1024 + tid;
        #pragma unroll
        for (int r = 0; r < 4; r++)
            v[r] = reinterpret_cast<const float4*>(x)[base + r * 256];
        #pragma unroll
        for (int r = 0; r < 4; r++) {
            const int idx = base + r * 256;
            const int row = idx >> 8;
            const int c4  = idx & 255;
            *reinterpret_cast<float4*>(&out[row * OUTW + c4 * 4]) = v[r];
            reinterpret_cast<__nv_bfloat162*>(xb)[idx * 2] =
                __floats2bfloat162_rn(v[r].x, v[r].y);
            reinterpret_cast<__nv_bfloat162*>(xb)[idx * 2 + 1] =
                __floats2bfloat162_rn(v[r].z, v[r].w);
        }
    }
}

// ---------------------------------------------------------------------------
// HMMA GEMM (R8-identical core), 3-stage cp.async; B via ldmatrix.trans.
// Epilogue scales by log2(e) so pairwise can use ex2 directly.
// CTA tile M=32 x N=64, BK=64 (16 chunks). Grid (16 nt, 8 mt) = 128 CTAs.
// ---------------------------------------------------------------------------
#define STAGE_BYTES 12288
#define GEMM_SMEM   (3 * STAGE_BYTES)

__global__ __launch_bounds__(256) void gemm_mma_kernel(
    const __nv_bfloat16* __restrict__ A, const __nv_bfloat16* __restrict__ Tb,
    __half* __restrict__ C)
{
    extern __shared__ __align__(1024) char dsm[];

    const int tid = threadIdx.x;
    const int wid = tid >> 5;
    const int lid = tid & 31;
    const int nt = blockIdx.x;
    const int mt = blockIdx.y;
    const int w_m = wid >> 2;
    const int w_n = wid & 3;

    const uint32_t sbase = smem_u32(dsm);

    const __nv_bfloat16* Ag = A + (size_t)(mt * 32) * INF;
    const __nv_bfloat16* Bg = Tb + nt * 64;

    const int ld_row  = tid >> 3;
    const int ld_kc   = tid & 7;
    const uint32_t soff0 = SWZ128((uint32_t)(ld_row * 128 + ld_kc * 16));
    const uint32_t soff1 = SWZ128((uint32_t)((ld_row + 32) * 128 + ld_kc * 16));

    float c[2][4];
    #pragma unroll
    for (int j = 0; j < 2; j++)
        #pragma unroll
        for (int q = 0; q < 4; q++) c[j][q] = 0.0f;

    const int l7  = lid & 7;
    const int lb3 = (lid >> 3) & 1;
    const int lb4 = (lid >> 4) & 1;
    const int a_row_lane = l7 + lb3 * 8;
    const int b_row_lane = l7 + lb3 * 8;
    const int nb = w_n * 16;
    const int mb = w_m * 16;
    const uint32_t b_col_bytes = (uint32_t)(nb + 8 * lb4) * 2;

    auto load_stage = [&](int st, int k0) {
        const uint32_t sA = sbase + st * STAGE_BYTES;
        const uint32_t sB = sA + 4096;
        const __nv_bfloat16* ga = Ag + ld_row * INF + k0 + ld_kc * 8;
        const __nv_bfloat16* gb = Bg + (size_t)(k0 + ld_row) * NCOLS + ld_kc * 8;
        CP_ASYNC16(sA + soff0, ga);
        CP_ASYNC16(sB + soff0, gb);
        CP_ASYNC16(sB + soff1, gb + 32 * NCOLS);
    };

    load_stage(0, 0);   CP_COMMIT();
    load_stage(1, 64);  CP_COMMIT();

    for (int ch = 0; ch < 16; ch++) {
        CP_WAIT1();
        __syncthreads();
        if (ch + 2 < 16) load_stage((ch + 2) % 3, (ch + 2) * 64);
        CP_COMMIT();

        const uint32_t sA = sbase + (ch % 3) * STAGE_BYTES;
        const uint32_t sB = sA + 4096;

        #pragma unroll
        for (int s = 0; s < 4; s++) {
            uint32_t b0, b1, b2, b3;
            {
                const uint32_t boff = SWZ128(
                    (uint32_t)((s * 16 + b_row_lane) * 128) + b_col_bytes);
                asm volatile(
                    "ldmatrix.sync.aligned.m8n8.x4.trans.shared.b16 {%0,%1,%2,%3}, [%4];"
                    : "=r"(b0), "=r"(b1), "=r"(b2), "=r"(b3) : "r"(sB + boff));
            }
            uint32_t a0, a1, a2, a3;
            {
                const uint32_t aoff = SWZ128(
                    (uint32_t)((mb + a_row_lane) * 128 + (s * 2 + lb4) * 16));
                asm volatile(
                    "ldmatrix.sync.aligned.m8n8.x4.shared.b16 {%0,%1,%2,%3}, [%4];"
                    : "=r"(a0), "=r"(a1), "=r"(a2), "=r"(a3) : "r"(sA + aoff));
            }
            asm volatile(
                "mma.sync.aligned.m16n8k16.row.col.f32.bf16.bf16.f32 "
                "{%0,%1,%2,%3}, {%4,%5,%6,%7}, {%8,%9}, {%0,%1,%2,%3};"
                : "+f"(c[0][0]), "+f"(c[0][1]), "+f"(c[0][2]), "+f"(c[0][3])
                : "r"(a0), "r"(a1), "r"(a2), "r"(a3), "r"(b0), "r"(b1));
            asm volatile(
                "mma.sync.aligned.m16n8k16.row.col.f32.bf16.bf16.f32 "
                "{%0,%1,%2,%3}, {%4,%5,%6,%7}, {%8,%9}, {%0,%1,%2,%3};"
                : "+f"(c[1][0]), "+f"(c[1][1]), "+f"(c[1][2]), "+f"(c[1][3])
                : "r"(a0), "r"(a1), "r"(a2), "r"(a3), "r"(b2), "r"(b3));
        }
    }

    const float LOG2E = 1.4426950408889634f;
    const int g = lid >> 2;
    const int tig = lid & 3;
    const int row = mt * 32 + mb + g;
    #pragma unroll
    for (int nf = 0; nf < 2; nf++) {
        const int col = nt * 64 + nb + nf * 8 + tig * 2;
        *reinterpret_cast<__half2*>(&C[row * NCOLS + col]) =
            __floats2half2_rn(c[nf][0] * LOG2E, c[nf][1] * LOG2E);
        *reinterpret_cast<__half2*>(&C[(row + 8) * NCOLS + col]) =
            __floats2half2_rn(c[nf][2] * LOG2E, c[nf][3] * LOG2E);
    }
}

// ---------------------------------------------------------------------------
// Pairwise, fp16x2 with lanes = TWO j's (no horizontal reduce per j).
// Mh is prescaled by log2(e): c = sum_j ex2(-d') - 1.
// Grid 512 = (o, i-quarter). 512 threads = 64 i-local x 8-way jp-split
// (16 pairs = 32 j each).
// Smem: Msp[pair][k] half2, lane0 = j even, lane1 = j odd. 4KB.
// ---------------------------------------------------------------------------
__global__ __launch_bounds__(512) void pairwise_kernel(
    const __half* __restrict__ Mh, float* __restrict__ out)
{
    const int o  = blockIdx.x >> 2;
    const int iq = blockIdx.x & 3;
    const int il = threadIdx.x & 63;
    const int h  = threadIdx.x >> 6;          // 0..7
    const int i  = iq * 64 + il;
    const int tid = threadIdx.x;

    __shared__ __align__(16) __half2 Msp[128][8];   // [pair][k]
    __shared__ float psum[7][64];

    // Stage: thread t (t<256) loads row t's 8 halfs for feature o, scatters
    // into lane (t&1) of pair (t>>1).
    if (tid < BATCH) {
        const uint4 rv = *reinterpret_cast<const uint4*>(&Mh[tid * NCOLS + o * KD]);
        const __half* hv = reinterpret_cast<const __half*>(&rv);
        const int p = tid >> 1, lane = tid & 1;
        #pragma unroll
        for (int k = 0; k < 8; k++)
            reinterpret_cast<__half*>(&Msp[p][k])[lane] = hv[k];
    }
    __syncthreads();

    // Own row, broadcast each k to both lanes.
    __half2 a[8];
    {
        const int p = i >> 1, lane = i & 1;
        #pragma unroll
        for (int k = 0; k < 8; k++)
            a[k] = __half2half2(reinterpret_cast<const __half*>(&Msp[p][k])[lane]);
    }

    __half2 acc = __float2half2_rn(0.0f);
    const int jp0 = h * 16;
    #pragma unroll 4
    for (int jp = jp0; jp < jp0 + 16; jp++) {
        const uint4* bp = reinterpret_cast<const uint4*>(&Msp[jp][0]);  // warp-uniform
        const uint4 u0 = bp[0];
        const uint4 u1 = bp[1];
        const __half2* b = reinterpret_cast<const __half2*>(&u0);
        const __half2* b2 = reinterpret_cast<const __half2*>(&u1);

        const __half2 t0 = __hadd2(__habs2(__hsub2(a[0], b[0])),
                                   __habs2(__hsub2(a[1], b[1])));
        const __half2 t1 = __hadd2(__habs2(__hsub2(a[2], b[2])),
                                   __habs2(__hsub2(a[3], b[3])));
        const __half2 t2 = __hadd2(__habs2(__hsub2(a[4], b2[0])),
                                   __habs2(__hsub2(a[5], b2[1])));
        const __half2 t3 = __hadd2(__habs2(__hsub2(a[6], b2[2])),
                                   __habs2(__hsub2(a[7], b2[3])));
        const __half2 d = __hadd2(__hadd2(t0, t1), __hadd2(t2, t3));  // per-lane dist
        const __half2 arg = __hneg2(d);                               // -d' (XOR)
        __half2 e;
        asm("ex2.approx.f16x2 %0, %1;"
            : "=r"(*reinterpret_cast<uint32_t*>(&e))
            : "r"(*reinterpret_cast<const uint32_t*>(&arg)));
        acc = __hadd2(acc, e);                                        // both j's
    }

    const float s = __low2float(acc) + __high2float(acc);

    if (h) psum[h - 1][il] = s;
    __syncthreads();
    if (h == 0) {
        float tot = s - 1.0f;
        #pragma unroll
        for (int q = 0; q < 7; q++) tot += psum[q][il];
        out[i * OUTW + INF + o] = tot;
    }
}

// ---------------------------------------------------------------------------
extern "C" void kernel_launch(void* const* d_in, const int* in_sizes, int n_in,
                              void* d_out, int out_size)
{
    const float* x = (const float*)d_in[0];   // (256, 1024)
    const float* T = (const float*)d_in[1];   // (1024, 1024)
    float* out = (float*)d_out;               // (256, 1152)

    __half* Mh;
    __nv_bfloat16 *Abf, *Tbf;
    cudaGetSymbolAddress((void**)&Mh, g_Mh);
    cudaGetSymbolAddress((void**)&Abf, g_Abf);
    cudaGetSymbolAddress((void**)&Tbf, g_Tbf);

    static bool attr_set = false;
    if (!attr_set) {
        cudaFuncSetAttribute(gemm_mma_kernel,
                             cudaFuncAttributeMaxDynamicSharedMemorySize, GEMM_SMEM);
        attr_set = true;
    }

    prep_kernel<<<320, 256>>>(x, T, out, Abf, Tbf);

    gemm_mma_kernel<<<dim3(NCOLS / 64, BATCH / 32), 256, GEMM_SMEM>>>(Abf, Tbf, Mh);

    pairwise_kernel<<<4 * OUTF, 512>>>(Mh, out);
}

// round 14
// speedup vs baseline: 1.4174x; 1.0017x over previous
#include <cuda_runtime.h>
#include <cuda_bf16.h>
#include <cuda_fp16.h>
#include <cstdint>

#define BATCH 256
#define INF   1024
#define OUTF  128
#define KD    8
#define NCOLS (OUTF * KD)     // 1024
#define OUTW  (INF + OUTF)    // 1152

// Device scratch (no allocs allowed)
__device__ __align__(16) __half g_Mh[BATCH * NCOLS];   // Mh = (x @ T) * log2(e), fp16
__device__ __nv_bfloat16 g_Abf[BATCH * INF];           // x in bf16 (K-major)
__device__ __nv_bfloat16 g_Tbf[INF * NCOLS];           // T in bf16, [k][n] layout

__device__ __forceinline__ uint32_t smem_u32(const void* p) {
    uint32_t a;
    asm("{ .reg .u64 t; cvta.to.shared.u64 t, %1; cvt.u32.u64 %0, t; }" : "=r"(a) : "l"(p));
    return a;
}
#define SWZ128(b) ((b) ^ (((b) >> 3) & 0x70))
#define CP_ASYNC16(saddr, gptr) \
    asm volatile("cp.async.cg.shared.global [%0], [%1], 16;" :: "r"(saddr), "l"(gptr) : "memory")
#define CP_COMMIT() asm volatile("cp.async.commit_group;" ::: "memory")
#define CP_WAIT1()  asm volatile("cp.async.wait_group 1;" ::: "memory")

// ---------------------------------------------------------------------------
// Streaming prep (R13-identical), MLP=4, 320 blocks.
// ---------------------------------------------------------------------------
__global__ __launch_bounds__(256) void prep_kernel(
    const float* __restrict__ x, const float* __restrict__ T,
    float* __restrict__ out, __nv_bfloat16* __restrict__ xb,
    __nv_bfloat16* __restrict__ Tb)
{
    const int tid = threadIdx.x;
    float4 v[4];
    if (blockIdx.x < 256) {
        const int base = blockIdx.x * 1024 + tid;
        #pragma unroll
        for (int r = 0; r < 4; r++)
            v[r] = reinterpret_cast<const float4*>(T)[base + r * 256];
        #pragma unroll
        for (int r = 0; r < 4; r++) {
            const int idx = base + r * 256;
            reinterpret_cast<__nv_bfloat162*>(Tb)[idx * 2] =
                __floats2bfloat162_rn(v[r].x, v[r].y);
            reinterpret_cast<__nv_bfloat162*>(Tb)[idx * 2 + 1] =
                __floats2bfloat162_rn(v[r].z, v[r].w);
        }
    } else {
        const int base = (blockIdx.x - 256) * 1024 + tid;
        #pragma unroll
        for (int r = 0; r < 4; r++)
            v[r] = reinterpret_cast<const float4*>(x)[base + r * 256];
        #pragma unroll
        for (int r = 0; r < 4; r++) {
            const int idx = base + r * 256;
            const int row = idx >> 8;
            const int c4  = idx & 255;
            *reinterpret_cast<float4*>(&out[row * OUTW + c4 * 4]) = v[r];
            reinterpret_cast<__nv_bfloat162*>(xb)[idx * 2] =
                __floats2bfloat162_rn(v[r].x, v[r].y);
            reinterpret_cast<__nv_bfloat162*>(xb)[idx * 2 + 1] =
                __floats2bfloat162_rn(v[r].z, v[r].w);
        }
    }
}

// ---------------------------------------------------------------------------
// HMMA GEMM (R13-identical), 3-stage cp.async; B via ldmatrix.trans.
// Epilogue scales by log2(e).
// ---------------------------------------------------------------------------
#define STAGE_BYTES 12288
#define GEMM_SMEM   (3 * STAGE_BYTES)

__global__ __launch_bounds__(256) void gemm_mma_kernel(
    const __nv_bfloat16* __restrict__ A, const __nv_bfloat16* __restrict__ Tb,
    __half* __restrict__ C)
{
    extern __shared__ __align__(1024) char dsm[];

    const int tid = threadIdx.x;
    const int wid = tid >> 5;
    const int lid = tid & 31;
    const int nt = blockIdx.x;
    const int mt = blockIdx.y;
    const int w_m = wid >> 2;
    const int w_n = wid & 3;

    const uint32_t sbase = smem_u32(dsm);

    const __nv_bfloat16* Ag = A + (size_t)(mt * 32) * INF;
    const __nv_bfloat16* Bg = Tb + nt * 64;

    const int ld_row  = tid >> 3;
    const int ld_kc   = tid & 7;
    const uint32_t soff0 = SWZ128((uint32_t)(ld_row * 128 + ld_kc * 16));
    const uint32_t soff1 = SWZ128((uint32_t)((ld_row + 32) * 128 + ld_kc * 16));

    float c[2][4];
    #pragma unroll
    for (int j = 0; j < 2; j++)
        #pragma unroll
        for (int q = 0; q < 4; q++) c[j][q] = 0.0f;

    const int l7  = lid & 7;
    const int lb3 = (lid >> 3) & 1;
    const int lb4 = (lid >> 4) & 1;
    const int a_row_lane = l7 + lb3 * 8;
    const int b_row_lane = l7 + lb3 * 8;
    const int nb = w_n * 16;
    const int mb = w_m * 16;
    const uint32_t b_col_bytes = (uint32_t)(nb + 8 * lb4) * 2;

    auto load_stage = [&](int st, int k0) {
        const uint32_t sA = sbase + st * STAGE_BYTES;
        const uint32_t sB = sA + 4096;
        const __nv_bfloat16* ga = Ag + ld_row * INF + k0 + ld_kc * 8;
        const __nv_bfloat16* gb = Bg + (size_t)(k0 + ld_row) * NCOLS + ld_kc * 8;
        CP_ASYNC16(sA + soff0, ga);
        CP_ASYNC16(sB + soff0, gb);
        CP_ASYNC16(sB + soff1, gb + 32 * NCOLS);
    };

    load_stage(0, 0);   CP_COMMIT();
    load_stage(1, 64);  CP_COMMIT();

    for (int ch = 0; ch < 16; ch++) {
        CP_WAIT1();
        __syncthreads();
        if (ch + 2 < 16) load_stage((ch + 2) % 3, (ch + 2) * 64);
        CP_COMMIT();

        const uint32_t sA = sbase + (ch % 3) * STAGE_BYTES;
        const uint32_t sB = sA + 4096;

        #pragma unroll
        for (int s = 0; s < 4; s++) {
            uint32_t b0, b1, b2, b3;
            {
                const uint32_t boff = SWZ128(
                    (uint32_t)((s * 16 + b_row_lane) * 128) + b_col_bytes);
                asm volatile(
                    "ldmatrix.sync.aligned.m8n8.x4.trans.shared.b16 {%0,%1,%2,%3}, [%4];"
                    : "=r"(b0), "=r"(b1), "=r"(b2), "=r"(b3) : "r"(sB + boff));
            }
            uint32_t a0, a1, a2, a3;
            {
                const uint32_t aoff = SWZ128(
                    (uint32_t)((mb + a_row_lane) * 128 + (s * 2 + lb4) * 16));
                asm volatile(
                    "ldmatrix.sync.aligned.m8n8.x4.shared.b16 {%0,%1,%2,%3}, [%4];"
                    : "=r"(a0), "=r"(a1), "=r"(a2), "=r"(a3) : "r"(sA + aoff));
            }
            asm volatile(
                "mma.sync.aligned.m16n8k16.row.col.f32.bf16.bf16.f32 "
                "{%0,%1,%2,%3}, {%4,%5,%6,%7}, {%8,%9}, {%0,%1,%2,%3};"
                : "+f"(c[0][0]), "+f"(c[0][1]), "+f"(c[0][2]), "+f"(c[0][3])
                : "r"(a0), "r"(a1), "r"(a2), "r"(a3), "r"(b0), "r"(b1));
            asm volatile(
                "mma.sync.aligned.m16n8k16.row.col.f32.bf16.bf16.f32 "
                "{%0,%1,%2,%3}, {%4,%5,%6,%7}, {%8,%9}, {%0,%1,%2,%3};"
                : "+f"(c[1][0]), "+f"(c[1][1]), "+f"(c[1][2]), "+f"(c[1][3])
                : "r"(a0), "r"(a1), "r"(a2), "r"(a3), "r"(b2), "r"(b3));
        }
    }

    const float LOG2E = 1.4426950408889634f;
    const int g = lid >> 2;
    const int tig = lid & 3;
    const int row = mt * 32 + mb + g;
    #pragma unroll
    for (int nf = 0; nf < 2; nf++) {
        const int col = nt * 64 + nb + nf * 8 + tig * 2;
        *reinterpret_cast<__half2*>(&C[row * NCOLS + col]) =
            __floats2half2_rn(c[nf][0] * LOG2E, c[nf][1] * LOG2E);
        *reinterpret_cast<__half2*>(&C[(row + 8) * NCOLS + col]) =
            __floats2half2_rn(c[nf][2] * LOG2E, c[nf][3] * LOG2E);
    }
}

// ---------------------------------------------------------------------------
// Pairwise, fp16x2, lanes = two j's; FOUR j's per iteration via two
// independent accumulator chains (hides LDS/MUFU/HADD2 latency).
// Grid 512 = (o, i-quarter). 512 threads = 64 i-local x 8-way jp-split.
// ---------------------------------------------------------------------------
__global__ __launch_bounds__(512) void pairwise_kernel(
    const __half* __restrict__ Mh, float* __restrict__ out)
{
    const int o  = blockIdx.x >> 2;
    const int iq = blockIdx.x & 3;
    const int il = threadIdx.x & 63;
    const int h  = threadIdx.x >> 6;          // 0..7
    const int i  = iq * 64 + il;
    const int tid = threadIdx.x;

    __shared__ __align__(16) __half2 Msp[128][8];   // [pair][k], lane = j parity
    __shared__ float psum[7][64];

    if (tid < BATCH) {
        const uint4 rv = *reinterpret_cast<const uint4*>(&Mh[tid * NCOLS + o * KD]);
        const __half* hv = reinterpret_cast<const __half*>(&rv);
        const int p = tid >> 1, lane = tid & 1;
        #pragma unroll
        for (int k = 0; k < 8; k++)
            reinterpret_cast<__half*>(&Msp[p][k])[lane] = hv[k];
    }
    __syncthreads();

    __half2 a[8];
    {
        const int p = i >> 1, lane = i & 1;
        #pragma unroll
        for (int k = 0; k < 8; k++)
            a[k] = __half2half2(reinterpret_cast<const __half*>(&Msp[p][k])[lane]);
    }

    __half2 accA = __float2half2_rn(0.0f);
    __half2 accB = __float2half2_rn(0.0f);
    const int jp0 = h * 16;

    #pragma unroll
    for (int it = 0; it < 8; it++) {
        const int jp = jp0 + it * 2;
        const uint4* bpA = reinterpret_cast<const uint4*>(&Msp[jp][0]);     // uniform
        const uint4* bpB = reinterpret_cast<const uint4*>(&Msp[jp + 1][0]); // uniform
        const uint4 uA0 = bpA[0], uA1 = bpA[1];
        const uint4 uB0 = bpB[0], uB1 = bpB[1];
        const __half2* bA = reinterpret_cast<const __half2*>(&uA0);
        const __half2* bA2 = reinterpret_cast<const __half2*>(&uA1);
        const __half2* bB = reinterpret_cast<const __half2*>(&uB0);
        const __half2* bB2 = reinterpret_cast<const __half2*>(&uB1);

        // chain A (j pair jp)
        const __half2 tA0 = __hadd2(__habs2(__hsub2(a[0], bA[0])),
                                    __habs2(__hsub2(a[1], bA[1])));
        const __half2 tA1 = __hadd2(__habs2(__hsub2(a[2], bA[2])),
                                    __habs2(__hsub2(a[3], bA[3])));
        const __half2 tA2 = __hadd2(__habs2(__hsub2(a[4], bA2[0])),
                                    __habs2(__hsub2(a[5], bA2[1])));
        const __half2 tA3 = __hadd2(__habs2(__hsub2(a[6], bA2[2])),
                                    __habs2(__hsub2(a[7], bA2[3])));
        const __half2 dA = __hadd2(__hadd2(tA0, tA1), __hadd2(tA2, tA3));
        const __half2 nA = __hneg2(dA);
        __half2 eA;
        asm("ex2.approx.f16x2 %0, %1;"
            : "=r"(*reinterpret_cast<uint32_t*>(&eA))
            : "r"(*reinterpret_cast<const uint32_t*>(&nA)));

        // chain B (j pair jp+1) — fully independent
        const __half2 tB0 = __hadd2(__habs2(__hsub2(a[0], bB[0])),
                                    __habs2(__hsub2(a[1], bB[1])));
        const __half2 tB1 = __hadd2(__habs2(__hsub2(a[2], bB[2])),
                                    __habs2(__hsub2(a[3], bB[3])));
        const __half2 tB2 = __hadd2(__habs2(__hsub2(a[4], bB2[0])),
                                    __habs2(__hsub2(a[5], bB2[1])));
        const __half2 tB3 = __hadd2(__habs2(__hsub2(a[6], bB2[2])),
                                    __habs2(__hsub2(a[7], bB2[3])));
        const __half2 dB = __hadd2(__hadd2(tB0, tB1), __hadd2(tB2, tB3));
        const __half2 nB = __hneg2(dB);
        __half2 eB;
        asm("ex2.approx.f16x2 %0, %1;"
            : "=r"(*reinterpret_cast<uint32_t*>(&eB))
            : "r"(*reinterpret_cast<const uint32_t*>(&nB)));

        accA = __hadd2(accA, eA);
        accB = __hadd2(accB, eB);
    }

    const __half2 acc = __hadd2(accA, accB);
    const float s = __low2float(acc) + __high2float(acc);

    if (h) psum[h - 1][il] = s;
    __syncthreads();
    if (h == 0) {
        float tot = s - 1.0f;
        #pragma unroll
        for (int q = 0; q < 7; q++) tot += psum[q][il];
        out[i * OUTW + INF + o] = tot;
    }
}

// ---------------------------------------------------------------------------
extern "C" void kernel_launch(void* const* d_in, const int* in_sizes, int n_in,
                              void* d_out, int out_size)
{
    const float* x = (const float*)d_in[0];   // (256, 1024)
    const float* T = (const float*)d_in[1];   // (1024, 1024)
    float* out = (float*)d_out;               // (256, 1152)

    __half* Mh;
    __nv_bfloat16 *Abf, *Tbf;
    cudaGetSymbolAddress((void**)&Mh, g_Mh);
    cudaGetSymbolAddress((void**)&Abf, g_Abf);
    cudaGetSymbolAddress((void**)&Tbf, g_Tbf);

    static bool attr_set = false;
    if (!attr_set) {
        cudaFuncSetAttribute(gemm_mma_kernel,
                             cudaFuncAttributeMaxDynamicSharedMemorySize, GEMM_SMEM);
        attr_set = true;
    }

    prep_kernel<<<320, 256>>>(x, T, out, Abf, Tbf);

    gemm_mma_kernel<<<dim3(NCOLS / 64, BATCH / 32), 256, GEMM_SMEM>>>(Abf, Tbf, Mh);

    pairwise_kernel<<<4 * OUTF, 512>>>(Mh, out);
}